// round 17
// baseline (speedup 1.0000x reference)
#include <cuda_runtime.h>
#include <math.h>

#define BB 4
#define NN 128
#define FF 128
#define SS 5
#define TGLOB 32
#define LL 2
#define TBL 256
#define LMAX 16.0f
#define TBL_SCALE (TBL / LMAX)
#define TBLK (TBL / 8)          /* table blocks per layer = 32 */

typedef unsigned long long ull;

__device__ __forceinline__ ull f2fma(ull a, ull b, ull c) {
    ull d; asm("fma.rn.f32x2 %0,%1,%2,%3;" : "=l"(d) : "l"(a), "l"(b), "l"(c)); return d;
}
__device__ __forceinline__ ull f2mul(ull a, ull b) {
    ull d; asm("mul.rn.f32x2 %0,%1,%2;" : "=l"(d) : "l"(a), "l"(b)); return d;
}
__device__ __forceinline__ ull f2add(ull a, ull b) {
    ull d; asm("add.rn.f32x2 %0,%1,%2;" : "=l"(d) : "l"(a), "l"(b)); return d;
}
__device__ __forceinline__ float2 upk(ull v) {
    float2 r; asm("mov.b64 {%0,%1},%2;" : "=f"(r.x), "=f"(r.y) : "l"(v)); return r;
}

// ---------------- persistent scratch (device globals; no allocation) ------
__device__ float g_posbuf[2][BB * NN * 3];
// per (bn, cp): 8 floats (v0c0,v0c1, v1c0,v1c1, v2c0,v2c1, zc0,zc1)
__device__ float g_veczf[2][BB * NN * 64 * 8];
// per (layer, t, cp): 4 floats (ell0 c0, ell0 c1, ell1 c0, ell1 c1)
// ell0 pre-scaled 1/16, ell1 pre-scaled sqrt(3)/16
__device__ float g_tblf[LL * TBL * 256];

// ---------------- fused prep: radial tables (fp32) + embed/init -----------
__global__ __launch_bounds__(512) void k_prep(const float* __restrict__ Wr1,
                                              const float* __restrict__ br1,
                                              const float* __restrict__ Wr2,
                                              const float* __restrict__ positions,
                                              const int* __restrict__ node_features,
                                              const float* __restrict__ gf,
                                              const float* __restrict__ W_embed,
                                              const float* __restrict__ b_embed,
                                              const float* __restrict__ Wnode) {
    const int tid = threadIdx.x;
    __shared__ float scr[7168];
    if (blockIdx.x < TBLK * LL) {
        // ---- table block: 8 rows, m split 4-way ----
        const int i = blockIdx.x / TBLK;
        const int tb0 = (blockIdx.x % TBLK) * 8;
        const int c = tid & 127;
        const int qm = tid >> 7;
        float* h = scr;                   // [8][64]
        float* redt = scr + 512;          // [3][8][2][128] = 6144
        if (tid < 64) {
            float w1 = Wr1[i * 64 + tid];
            float b1 = br1[i * 64 + tid];
#pragma unroll
            for (int j = 0; j < 8; j++) {
                float lng = (float)(tb0 + j) * (LMAX / (float)TBL);
                float pv = lng * w1 + b1;
                h[j * 64 + tid] = pv / (1.0f + expf(-pv));
            }
        }
        __syncthreads();
        const float* W = Wr2 + i * 64 * 512 + c;
        float acc[8][2];
#pragma unroll
        for (int j = 0; j < 8; j++) { acc[j][0] = 0.f; acc[j][1] = 0.f; }
#pragma unroll 4
        for (int mm = 0; mm < 16; mm++) {
            int m = qm * 16 + mm;
            float w0 = W[m * 512 + 0];
            float w1v = W[m * 512 + 128];
#pragma unroll
            for (int j = 0; j < 8; j++) {
                float hm = h[j * 64 + m];
                acc[j][0] = fmaf(hm, w0, acc[j][0]);
                acc[j][1] = fmaf(hm, w1v, acc[j][1]);
            }
        }
        if (qm > 0) {
#pragma unroll
            for (int j = 0; j < 8; j++) {
                redt[((qm - 1) * 8 + j) * 256 + c]       = acc[j][0];
                redt[((qm - 1) * 8 + j) * 256 + 128 + c] = acc[j][1];
            }
        }
        __syncthreads();
        if (qm == 0) {
            const float sc0 = 1.0f / 16.0f;
            const float sc1 = 1.7320508075688772f / 16.0f;
#pragma unroll
            for (int j = 0; j < 8; j++) {
                float f0 = (acc[j][0] + redt[j * 256 + c] + redt[(8 + j) * 256 + c]
                            + redt[(16 + j) * 256 + c]) * sc0;
                float f1 = (acc[j][1] + redt[j * 256 + 128 + c] + redt[(8 + j) * 256 + 128 + c]
                            + redt[(16 + j) * 256 + 128 + c]) * sc1;
                float e0hi = __shfl_down_sync(0xffffffffu, f0, 1);
                float e1hi = __shfl_down_sync(0xffffffffu, f1, 1);
                if ((c & 1) == 0) {
                    float4 v = make_float4(f0, e0hi, f1, e1hi);
                    *(float4*)(g_tblf + (size_t)(i * TBL + tb0 + j) * 256 + (c >> 1) * 4) = v;
                }
            }
        }
    } else {
        // ---- init block: 4 nodes ----
        const int bn0 = (blockIdx.x - TBLK * LL) * 4;
        const int n = tid >> 7;
        const int c = tid & 127;
        const int bn = bn0 + n;
        const int b = bn / NN;
        float* srow = scr;                // [4][128]
        float* partz = scr + 512;         // [4][4][128]

        int nf = node_features[bn];
        float s = W_embed[(nf - 1) * FF + c] + b_embed[c];
#pragma unroll 8
        for (int t = 0; t < TGLOB; t++)
            s = fmaf(gf[b * TGLOB + t], W_embed[(SS + t) * FF + c], s);
        srow[n * FF + c] = s;
        if (c < 3) g_posbuf[0][bn * 3 + c] = positions[bn * 3 + c];
        __syncthreads();

        const int lane = tid & 31;
        const int grp = tid >> 5;
        const int nz = grp >> 2;
        const int q4 = grp & 3;
        const int c4 = lane * 4;
        const float* W = Wnode + c4;
        float4 z = make_float4(0.f, 0.f, 0.f, 0.f);
#pragma unroll
        for (int kk = 0; kk < 32; kk++) {
            int k = q4 * 32 + kk;
            float4 w4 = *(const float4*)(W + k * FF);
            float sv = srow[nz * FF + k];
            z.x = fmaf(sv, w4.x, z.x); z.y = fmaf(sv, w4.y, z.y);
            z.z = fmaf(sv, w4.z, z.z); z.w = fmaf(sv, w4.w, z.w);
        }
        __syncthreads();
        *(float4*)&partz[(q4 * 4 + nz) * FF + c4] = z;
        __syncthreads();

        float zsum = partz[(0 * 4 + n) * FF + c] + partz[(1 * 4 + n) * FF + c]
                   + partz[(2 * 4 + n) * FF + c] + partz[(3 * 4 + n) * FF + c];
        float* dst = g_veczf[0] + ((size_t)bn * 64 + (c >> 1)) * 8 + (c & 1);
        dst[0] = 0.f; dst[2] = 0.f; dst[4] = 0.f; dst[6] = zsum;
    }
}

// ---------------- fused layer: msg (f32x2, 2 receivers) + node update -----
// grid (NN/2, BB); blockDim (64, 8): cp = channel pair, q = sender group of 16
__global__ __launch_bounds__(512, 2) void k_layer(const float* __restrict__ pos_in,
                                                  const float* __restrict__ c1w,
                                                  const float* __restrict__ c2w,
                                                  const float* __restrict__ c3w,
                                                  const float* __restrict__ Wmix0,
                                                  const float* __restrict__ Wmix1,
                                                  const float* __restrict__ Wg1,
                                                  const float* __restrict__ Wg2,
                                                  const float* __restrict__ Wvout,
                                                  const float* __restrict__ Wnode,
                                                  float* __restrict__ out,
                                                  int layer) {
    const int r0 = blockIdx.x * 2;
    const int b = blockIdx.y;
    const int cp = threadIdx.x;      // 0..63
    const int q = threadIdx.y;       // 0..7
    const int tid = q * 64 + cp;
    const int p = layer & 1;

    __shared__ float sp[NN * 3];
    __shared__ float sp0[NN * 3];
    __shared__ float4 sGa[2][NN];    // (ux,ux,uy,uy)
    __shared__ float4 sGb[2][NN];    // (uz,uz,a0,a0)
    __shared__ float2 sGc[2][NN];    // (a1,a1)
    __shared__ int    sIt[2][NN];
    __shared__ float rp[8 * 1024];   // msg: ull red [7][2][4][64]; node: part[8][2*512]
    __shared__ float sA[2 * 512];
    __shared__ float sred[2 * 512];
    __shared__ float shp[2][2][16];
    __shared__ float sh[2][16];
    __shared__ float rb[2][3][4];
    __shared__ float zred[2][FF];

    for (int idx = tid; idx < NN * 3; idx += 512) {
        sp[idx]  = g_posbuf[p][b * NN * 3 + idx];
        sp0[idx] = pos_in[b * NN * 3 + idx];
    }
    __syncthreads();

    // ---- phase 1: per-(receiver, sender) geometry, duplicated packs ----
    if (tid < 2 * NN) {
        const int rr = tid >> 7;
        const int s = tid & (NN - 1);
        const int r = r0 + rr;
        const float rx = sp[r * 3 + 0], ry = sp[r * 3 + 1], rz = sp[r * 3 + 2];
        float dx0 = sp0[r * 3 + 0] - sp0[s * 3 + 0];
        float dy0 = sp0[r * 3 + 1] - sp0[s * 3 + 1];
        float dz0 = sp0[r * 3 + 2] - sp0[s * 3 + 2];
        float l0 = sqrtf(dx0 * dx0 + dy0 * dy0 + dz0 * dz0 + 1e-12f);
        float env = (l0 < 10.0f) ? 0.5f * (cosf(l0 * 0.3141592653589793f) + 1.0f) : 0.0f;
        if (s == r) env = 0.0f;

        float vx = rx - sp[s * 3 + 0];
        float vy = ry - sp[s * 3 + 1];
        float vz = rz - sp[s * 3 + 2];
        float lng = sqrtf(vx * vx + vy * vy + vz * vz + 1e-12f);
        float inv = 1.0f / lng;
        float ux = vx * inv, uy = vy * inv, uz = vz * inv;

        float tp = fminf(lng * TBL_SCALE, (float)TBL - 1.001f);
        int it = (int)tp;
        float fr = tp - (float)it;
        float a0 = env * (1.0f - fr);
        float a1 = env * fr;

        sGa[rr][s] = make_float4(ux, ux, uy, uy);
        sGb[rr][s] = make_float4(uz, uz, a0, a0);
        sGc[rr][s] = make_float2(a1, a1);
        sIt[rr][s] = it;
    }
    __syncthreads();

    // ---- phase 2: f32x2 accumulation over senders ----
    ull A[2][4];
#pragma unroll
    for (int rr = 0; rr < 2; rr++)
#pragma unroll
        for (int k = 0; k < 4; k++) A[rr][k] = 0ull;

    {
        const float* tbf = g_tblf + (size_t)layer * TBL * 256;
        const float* vzf = g_veczf[p] + ((size_t)(b * NN) * 64 + cp) * 8;
#pragma unroll 2
        for (int s = q * 16; s < q * 16 + 16; s++) {
            const float* vz = vzf + (size_t)s * 512;
            ulonglong2 V0 = *(const ulonglong2*)vz;        // v0_2, v1_2
            ulonglong2 V1 = *(const ulonglong2*)(vz + 4);  // v2_2, z_2
#pragma unroll
            for (int rr = 0; rr < 2; rr++) {
                ulonglong2 L0 = *(const ulonglong2*)&sGa[rr][s];  // ux2, uy2
                ulonglong2 L1 = *(const ulonglong2*)&sGb[rr][s];  // uz2, a0_2
                ull a12 = *(const ull*)&sGc[rr][s];
                int it = sIt[rr][s];
                const float* tr = tbf + (size_t)it * 256 + (cp << 2);
                ulonglong2 T0 = *(const ulonglong2*)tr;           // e0_2, e1_2 @t
                ulonglong2 T1 = *(const ulonglong2*)(tr + 256);   // @t+1

                ull Rw0 = f2fma(L1.y, T0.x, f2mul(a12, T1.x));
                ull Rw1 = f2fma(L1.y, T0.y, f2mul(a12, T1.y));

                ull f2 = f2fma(V0.x, L0.x, V1.y);
                f2 = f2fma(V0.y, L0.y, f2);
                f2 = f2fma(V1.x, L1.x, f2);

                ull t0 = f2mul(Rw0, f2);
                ull t1 = f2mul(Rw1, f2);
                A[rr][0] = f2add(A[rr][0], t0);
                A[rr][1] = f2fma(t1, L0.x, A[rr][1]);
                A[rr][2] = f2fma(t1, L0.y, A[rr][2]);
                A[rr][3] = f2fma(t1, L1.x, A[rr][3]);
            }
        }
    }

    ull* rpu = (ull*)rp;
    if (q > 0) {
#pragma unroll
        for (int rr = 0; rr < 2; rr++)
#pragma unroll
            for (int k = 0; k < 4; k++)
                rpu[(q - 1) * 512 + rr * 256 + k * 64 + cp] = A[rr][k];
    }
    __syncthreads();

    if (q == 0) {
#pragma unroll
        for (int rr = 0; rr < 2; rr++) {
#pragma unroll
            for (int k = 0; k < 4; k++) {
#pragma unroll
                for (int qq = 0; qq < 7; qq++)
                    A[rr][k] = f2add(A[rr][k], rpu[qq * 512 + rr * 256 + k * 64 + cp]);
            }
            float2 a0 = upk(A[rr][0]);
            float2 a1 = upk(A[rr][1]);
            float2 a2 = upk(A[rr][2]);
            float2 a3 = upk(A[rr][3]);
#pragma unroll
            for (int hh = 0; hh < 2; hh++) {
                const int c = 2 * cp + hh;
                float A0 = hh ? a0.y : a0.x;
                float A1 = hh ? a1.y : a1.x;
                float A2 = hh ? a2.y : a2.x;
                float A3 = hh ? a3.y : a3.x;
                float n0 = A0 * A0;
                float n1 = A1 * A1 + A2 * A2 + A3 * A3;
                const int co = (layer * 4) * FF + c;
                float g0 = 1.f + c1w[co]      * n0 + c2w[co]      * n0 * n0 + c3w[co]      * n0 * n0 * n0;
                float g1 = 1.f + c1w[co + FF] * n1 + c2w[co + FF] * n1 * n1 + c3w[co + FF] * n1 * n1 * n1;
                sA[rr * 512 + c]          = A0 * g0;
                sA[rr * 512 + FF + c]     = A1 * g1;
                sA[rr * 512 + 2 * FF + c] = A2 * g1;
                sA[rr * 512 + 3 * FF + c] = A3 * g1;
            }
        }
    }
    __syncthreads();

    // ---- node phase: threads [0,256) -> node r0, [256,512) -> node r0+1 ----
    const int n = tid >> 8;
    const int t2 = tid & 255;
    const int lane = t2 & 31;
    const int q8 = t2 >> 5;
    const int c4 = lane * 4;
    const float* an = sA + n * 512;
    const int bn = b * NN + r0 + n;

    {
        const float* M0 = Wmix0 + layer * FF * FF + c4;
        const float* M1 = Wmix1 + layer * FF * FF + c4;
        float4 a0v = make_float4(0.f, 0.f, 0.f, 0.f);
        float4 a1v = a0v, a2v = a0v, a3v = a0v;
#pragma unroll
        for (int kk = 0; kk < 16; kk++) {
            int k = q8 * 16 + kk;
            float4 m0 = *(const float4*)(M0 + k * FF);
            float4 m1 = *(const float4*)(M1 + k * FF);
            float aS = an[k], b0 = an[FF + k], b1 = an[2 * FF + k], b2 = an[3 * FF + k];
            a0v.x = fmaf(aS, m0.x, a0v.x); a0v.y = fmaf(aS, m0.y, a0v.y);
            a0v.z = fmaf(aS, m0.z, a0v.z); a0v.w = fmaf(aS, m0.w, a0v.w);
            a1v.x = fmaf(b0, m1.x, a1v.x); a1v.y = fmaf(b0, m1.y, a1v.y);
            a1v.z = fmaf(b0, m1.z, a1v.z); a1v.w = fmaf(b0, m1.w, a1v.w);
            a2v.x = fmaf(b1, m1.x, a2v.x); a2v.y = fmaf(b1, m1.y, a2v.y);
            a2v.z = fmaf(b1, m1.z, a2v.z); a2v.w = fmaf(b1, m1.w, a2v.w);
            a3v.x = fmaf(b2, m1.x, a3v.x); a3v.y = fmaf(b2, m1.y, a3v.y);
            a3v.z = fmaf(b2, m1.z, a3v.z); a3v.w = fmaf(b2, m1.w, a3v.w);
        }
        float* pq = rp + q8 * 1024 + n * 512;
        *(float4*)&pq[0 * FF + c4] = a0v;
        *(float4*)&pq[1 * FF + c4] = a1v;
        *(float4*)&pq[2 * FF + c4] = a2v;
        *(float4*)&pq[3 * FF + c4] = a3v;
    }
    __syncthreads();

    for (int idx = t2; idx < 512; idx += 256) {
        float s = 0.f;
#pragma unroll
        for (int qq = 0; qq < 8; qq++) s += rp[qq * 1024 + n * 512 + idx];
        sred[n * 512 + idx] = s;
    }
    __syncthreads();

    if (t2 < 32) {
        int cc = t2 & 15, hf = t2 >> 4;
        const float* G1 = Wg1 + layer * FF * 16 + cc;
        const float* sn = sred + n * 512;
        float a = 0.f;
#pragma unroll 8
        for (int kk = 0; kk < 64; kk++) {
            int k = hf * 64 + kk;
            a = fmaf(sn[k], G1[k * 16], a);
        }
        shp[n][hf][cc] = a;
    }
    __syncthreads();
    if (t2 < 16) {
        float a = shp[n][0][t2] + shp[n][1][t2];
        sh[n][t2] = a / (1.0f + expf(-a));
    }
    __syncthreads();

    if (t2 < 128) {
        const float* G2 = Wg2 + layer * 16 * FF;
        float gate = 0.f;
#pragma unroll
        for (int j = 0; j < 16; j++) gate = fmaf(sh[n][j], G2[j * FF + t2], gate);
        float w = gate * Wvout[layer * FF + t2];
        const float* sn = sred + n * 512;
        float m0 = sn[FF + t2] * w;
        float m1 = sn[2 * FF + t2] * w;
        float m2 = sn[3 * FF + t2] * w;
#pragma unroll
        for (int off = 16; off > 0; off >>= 1) {
            m0 += __shfl_down_sync(0xffffffffu, m0, off);
            m1 += __shfl_down_sync(0xffffffffu, m1, off);
            m2 += __shfl_down_sync(0xffffffffu, m2, off);
        }
        if ((t2 & 31) == 0) {
            int wp = t2 >> 5;
            rb[n][0][wp] = m0; rb[n][1][wp] = m1; rb[n][2][wp] = m2;
        }
    }
    __syncthreads();
    if (t2 < 3) {
        float pnew = sp[(r0 + n) * 3 + t2]
                   + rb[n][t2][0] + rb[n][t2][1] + rb[n][t2][2] + rb[n][t2][3];
        g_posbuf[1 - p][bn * 3 + t2] = pnew;
        if (layer == LL - 1)
            out[bn * 3 + t2] = pnew - pos_in[bn * 3 + t2];
    }

    if (layer + 1 < LL) {
        const float* W = Wnode + (layer + 1) * FF * FF + c4;
        const float* sn = sred + n * 512;
        float4 zacc = make_float4(0.f, 0.f, 0.f, 0.f);
#pragma unroll
        for (int kk = 0; kk < 16; kk++) {
            int k = q8 * 16 + kk;
            float4 w4 = *(const float4*)(W + k * FF);
            float s = sn[k];
            zacc.x = fmaf(s, w4.x, zacc.x); zacc.y = fmaf(s, w4.y, zacc.y);
            zacc.z = fmaf(s, w4.z, zacc.z); zacc.w = fmaf(s, w4.w, zacc.w);
        }
        __syncthreads();
        *(float4*)&rp[q8 * 1024 + n * 512 + c4] = zacc;
        __syncthreads();
        if (t2 < 128) {
            float s = 0.f;
#pragma unroll
            for (int qq = 0; qq < 8; qq++) s += rp[qq * 1024 + n * 512 + t2];
            zred[n][t2] = s;
        }
        __syncthreads();
    }

    if (t2 < 128) {
        const float* sn = sred + n * 512;
        float zn = (layer + 1 < LL) ? zred[n][t2] : 0.f;
        float* dst = g_veczf[1 - p] + ((size_t)bn * 64 + (t2 >> 1)) * 8 + (t2 & 1);
        dst[0] = sn[FF + t2];
        dst[2] = sn[2 * FF + t2];
        dst[4] = sn[3 * FF + t2];
        dst[6] = zn;
    }
}

// ---------------------------------------------------------------------------
extern "C" void kernel_launch(void* const* d_in, const int* in_sizes, int n_in,
                              void* d_out, int out_size) {
    const float* positions     = (const float*)d_in[0];
    const int*   node_features = (const int*)d_in[1];
    const float* gf            = (const float*)d_in[2];
    const float* W_embed       = (const float*)d_in[3];
    const float* b_embed       = (const float*)d_in[4];
    const float* Wr1           = (const float*)d_in[5];
    const float* br1           = (const float*)d_in[6];
    const float* Wr2           = (const float*)d_in[7];
    const float* Wnode         = (const float*)d_in[8];
    const float* c1w           = (const float*)d_in[9];
    const float* c2w           = (const float*)d_in[10];
    const float* c3w           = (const float*)d_in[11];
    const float* Wmix0         = (const float*)d_in[12];
    const float* Wmix1         = (const float*)d_in[13];
    const float* Wg1           = (const float*)d_in[14];
    const float* Wg2           = (const float*)d_in[15];
    const float* Wvout         = (const float*)d_in[16];
    float* out = (float*)d_out;

    k_prep<<<TBLK * LL + BB * NN / 4, 512>>>(Wr1, br1, Wr2, positions, node_features,
                                             gf, W_embed, b_embed, Wnode);
    for (int i = 0; i < LL; i++)
        k_layer<<<dim3(NN / 2, BB), dim3(64, 8)>>>(positions, c1w, c2w, c3w,
                                                   Wmix0, Wmix1, Wg1, Wg2, Wvout,
                                                   Wnode, out, i);
}